// round 14
// baseline (speedup 1.0000x reference)
#include <cuda_runtime.h>
#include <cuda_fp16.h>
#include <stdint.h>

#define B_    8
#define NV_   128
#define NQ_   512
#define DIN   128
#define DPROJ 512
#define HD    256

#define PR_S  136
#define VW_S  264
#define SC_S  132
#define EB_S  136
#define VT_S  136
#define QS_S  264

#define NCTA  128

// ---- device scratch (allocations forbidden) ----
__device__ __half g_vw16[B_*NV_*DPROJ];   // v_*wa : [b*128+i][512]
__device__ __half g_vT16[B_*DPROJ*NV_];   // v_^T  : [b][512][128]
__device__ __half g_WqT [DPROJ*DIN];      // Wq^T f16 [512][128]
__device__ unsigned g_barC[1];            // accumulating barrier (replay-safe)

__device__ __forceinline__ void mma16816(float* c, const uint32_t* a, const uint32_t* b) {
    asm volatile(
        "mma.sync.aligned.m16n8k16.row.col.f32.f16.f16.f32 "
        "{%0,%1,%2,%3}, {%4,%5,%6,%7}, {%8,%9}, {%0,%1,%2,%3};\n"
        : "+f"(c[0]), "+f"(c[1]), "+f"(c[2]), "+f"(c[3])
        : "r"(a[0]), "r"(a[1]), "r"(a[2]), "r"(a[3]), "r"(b[0]), "r"(b[1]));
}

__device__ __forceinline__ void cp_async16(void* s, const void* g) {
    uint32_t sa = (uint32_t)__cvta_generic_to_shared(s);
    asm volatile("cp.async.cg.shared.global [%0], [%1], 16;" :: "r"(sa), "l"(g));
}
#define CP_COMMIT()  asm volatile("cp.async.commit_group;" ::: "memory")
#define CP_WAIT(n)   asm volatile("cp.async.wait_group %0;" :: "n"(n) : "memory")

// grid-wide barrier: replay-safe accumulating counter
__device__ __forceinline__ void grid_barrier() {
    __threadfence();
    __syncthreads();
    if (threadIdx.x == 0) {
        unsigned my = atomicAdd(&g_barC[0], 1u);
        unsigned tgt = (my / NCTA + 1u) * NCTA;
        unsigned cur;
        do {
            asm volatile("ld.acquire.gpu.u32 %0, [%1];"
                         : "=r"(cur) : "l"(g_barC));
        } while (cur < tgt);
    }
    __syncthreads();
}

// ============================================================
// Fused kernel: 128 CTAs x 512 thr, 222.5KB smem (1 CTA/SM, all resident).
// Phase A: all CTAs load q-in; bid<32 vproj; bid in [32,48) WqT transpose.
// Phase B: score pipeline (cp.async prefetch) per (jt,h,b).
// ============================================================
__global__ __launch_bounds__(512, 1) void ban_k(
    const float* __restrict__ v,  const float* __restrict__ q,
    const float* __restrict__ Wv, const float* __restrict__ Wq,
    const float* __restrict__ bv, const float* __restrict__ bq,
    const float* __restrict__ wa, const float* __restrict__ Wo,
    const float* __restrict__ bo, float* __restrict__ out)
{
    extern __shared__ __align__(16) char smem[];
    __half* X   = (__half*)smem;                  // prep: As ; score: WqT->vT [256][136]
    __half* VW  = (__half*)(smem + 69632);        // prep: Bs/WqT-stage ; score: vw [128][264]
    __half* qs  = (__half*)(smem + 137216);       // [64][264]
    float*  sc  = (float*) (smem + 171008);       // [64][132] ; later ph[256]
    __half* ebf = (__half*)(smem + 204800);       // q-in [64][136] -> exp [64][136]
    float*  inv = (float*) (smem + 222208);       // [64]

    int t = threadIdx.x;
    int bid = blockIdx.x;
    int jt = bid & 7, h = (bid >> 3) & 1, b = bid >> 4;
    int lane = t & 31, wid = t >> 5;
    int lr = lane >> 2, lc = (lane & 3)*2;
    float* att_out = out + B_*HD;

    // ================= phase A =================
    // all CTAs: load + convert q-in tile (independent of prep outputs)
    {
        __half* qin = ebf;
        #pragma unroll
        for (int it = 0; it < 4; it++) {
            int fi = t + it*512;                 // 2048 float4
            int m = fi >> 5, k = (fi & 31)*4;
            float4 f = *(const float4*)(q + (size_t)(b*NQ_ + jt*64 + m)*DIN + k);
            __half2 h0 = __floats2half2_rn(f.x, f.y);
            __half2 h1 = __floats2half2_rn(f.z, f.w);
            uint2 u; u.x = *(uint32_t*)&h0; u.y = *(uint32_t*)&h1;
            *(uint2*)(qin + m*PR_S + k) = u;
        }
    }

    if (bid < 32) {
        // ---- vproj: Wv transposed inline; emits vw and vT ----
        __half* As = X;                            // [128][136]
        __half* Bs = VW;                           // [128][136]
        int bn = (bid & 3) * 128;
        int my = bid >> 2;
        int bm = my * 128;

        #pragma unroll
        for (int it = 0; it < 8; it++) {
            int fi = t + it*512;
            int m = fi >> 5, k = (fi & 31)*4;
            float4 f = *(const float4*)(v + (size_t)(bm+m)*DIN + k);
            __half2 h0 = __floats2half2_rn(f.x, f.y);
            __half2 h1 = __floats2half2_rn(f.z, f.w);
            uint2 u; u.x = *(uint32_t*)&h0; u.y = *(uint32_t*)&h1;
            *(uint2*)(As + m*PR_S + k) = u;
        }
        #pragma unroll
        for (int it = 0; it < 32; it++) {
            int fi = t + it*512;
            int k = fi >> 7, n = fi & 127;
            Bs[n*PR_S + k] = __float2half(Wv[(size_t)k*DPROJ + bn + n]);
        }
        __syncthreads();

        int warpM = wid >> 2, warpN = wid & 3;
        float acc[2][4][4] = {};
        #pragma unroll
        for (int ks = 0; ks < 8; ks++) {
            int k0 = ks*16;
            uint32_t a[2][4], bb[4][2];
            #pragma unroll
            for (int mt = 0; mt < 2; mt++) {
                const __half* ab = As + (warpM*32 + mt*16 + lr)*PR_S + k0 + lc;
                a[mt][0] = *(const uint32_t*)ab;
                a[mt][1] = *(const uint32_t*)(ab + 8*PR_S);
                a[mt][2] = *(const uint32_t*)(ab + 8);
                a[mt][3] = *(const uint32_t*)(ab + 8*PR_S + 8);
            }
            #pragma unroll
            for (int nt = 0; nt < 4; nt++) {
                const __half* bp = Bs + (warpN*32 + nt*8 + lr)*PR_S + k0 + lc;
                bb[nt][0] = *(const uint32_t*)bp;
                bb[nt][1] = *(const uint32_t*)(bp + 8);
            }
            #pragma unroll
            for (int mt = 0; mt < 2; mt++)
                #pragma unroll
                for (int nt = 0; nt < 4; nt++)
                    mma16816(acc[mt][nt], a[mt], bb[nt]);
        }
        __syncthreads();   // As reused as transpose staging

        #pragma unroll
        for (int mt = 0; mt < 2; mt++) {
            int rowL = warpM*32 + mt*16 + lr;
            #pragma unroll
            for (int nt = 0; nt < 4; nt++) {
                int colL = warpN*32 + nt*8 + lc;
                int col = bn + colL;
                float b0 = bv[col], b1 = bv[col+1];
                float v00 = acc[mt][nt][0] + b0, v01 = acc[mt][nt][1] + b1;
                float v10 = acc[mt][nt][2] + b0, v11 = acc[mt][nt][3] + b1;
                int row = bm + rowL;
                float w0 = wa[col & 255], w1 = wa[(col+1) & 255];
                *(__half2*)(g_vw16 + (size_t)row*DPROJ + col) =
                    __floats2half2_rn(v00*w0, v01*w1);
                *(__half2*)(g_vw16 + (size_t)(row+8)*DPROJ + col) =
                    __floats2half2_rn(v10*w0, v11*w1);
                __half* tr = As;
                tr[colL*PR_S + rowL]       = __float2half(v00);
                tr[(colL+1)*PR_S + rowL]   = __float2half(v01);
                tr[colL*PR_S + rowL+8]     = __float2half(v10);
                tr[(colL+1)*PR_S + rowL+8] = __float2half(v11);
            }
        }
        __syncthreads();
        const __half* tr = As;
        #pragma unroll
        for (int it = 0; it < 4; it++) {
            int fi = t + it*512;
            int n = fi >> 4, k = (fi & 15)*8;
            *(float4*)(g_vT16 + ((size_t)my*DPROJ + bn + n)*NV_ + k) =
                *(const float4*)(tr + n*PR_S + k);
        }
    } else if (bid < 48) {
        // ---- Wq transpose: 16 CTAs x 32 cols ----
        __half* s = VW;                            // [32][136]
        int n0 = (bid - 32) * 32;
        if (bid == 32) {
            #pragma unroll
            for (int it = 0; it < 4; it++) out[t + it*512] = 0.f;
        }
        #pragma unroll
        for (int it = 0; it < 8; it++) {
            int fi = t + it*512;
            int k = fi >> 5, nn = fi & 31;
            s[nn*136 + k] = __float2half(Wq[(size_t)k*DPROJ + n0 + nn]);
        }
        __syncthreads();
        {
            int n = t >> 4, kq = (t & 15)*8;
            *(float4*)(g_WqT + (size_t)(n0 + n)*DIN + kq) = *(const float4*)(s + n*136 + kq);
        }
    }

    grid_barrier();

    // ================= phase B: score =================
    // ---- issue async loads: WqT (group A), vw (group B) ----
    {
        const __half* wqt = g_WqT + (size_t)(h*HD)*DIN;
        #pragma unroll
        for (int it = 0; it < 8; it++) {
            int fi = t + it*512;
            int n = fi >> 4, k = (fi & 15)*8;
            cp_async16(X + n*PR_S + k, wqt + (size_t)n*DIN + k);
        }
        CP_COMMIT();   // group A
        const __half* vwg = g_vw16 + ((size_t)b*NV_)*DPROJ + h*HD;
        #pragma unroll
        for (int it = 0; it < 8; it++) {
            int fi = t + it*512;
            int i = fi >> 5, k = (fi & 31)*8;
            cp_async16(VW + i*VW_S + k, vwg + (size_t)i*DPROJ + k);
        }
        CP_COMMIT();   // group B
    }
    CP_WAIT(1);          // A done
    __syncthreads();

    // -------- P0: q projection --------
    {
        __half* qin = ebf;
        int wj = wid >> 3, wd = wid & 7;
        float acc[2][4][4] = {};
        #pragma unroll
        for (int ks = 0; ks < 8; ks++) {
            int k0 = ks*16;
            uint32_t a[2][4], bb2[4][2];
            #pragma unroll
            for (int mt = 0; mt < 2; mt++) {
                const __half* ab = qin + (wj*32 + mt*16 + lr)*PR_S + k0 + lc;
                a[mt][0] = *(const uint32_t*)ab;
                a[mt][1] = *(const uint32_t*)(ab + 8*PR_S);
                a[mt][2] = *(const uint32_t*)(ab + 8);
                a[mt][3] = *(const uint32_t*)(ab + 8*PR_S + 8);
            }
            #pragma unroll
            for (int nt = 0; nt < 4; nt++) {
                const __half* bb = X + (wd*32 + nt*8 + lr)*PR_S + k0 + lc;
                bb2[nt][0] = *(const uint32_t*)bb;
                bb2[nt][1] = *(const uint32_t*)(bb + 8);
            }
            #pragma unroll
            for (int mt = 0; mt < 2; mt++)
                #pragma unroll
                for (int nt = 0; nt < 4; nt++)
                    mma16816(acc[mt][nt], a[mt], bb2[nt]);
        }
        __syncthreads();   // done reading X (WqT) and qin

        // ---- issue vT async into X (group C) ----
        {
            const __half* vtg = g_vT16 + ((size_t)b*DPROJ + h*HD)*NV_;
            #pragma unroll
            for (int it = 0; it < 8; it++) {
                int fi = t + it*512;
                int d = fi >> 4, k = (fi & 15)*8;
                cp_async16(X + d*VT_S + k, vtg + (size_t)d*NV_ + k);
            }
            CP_COMMIT();   // group C
        }

        #pragma unroll
        for (int mt = 0; mt < 2; mt++) {
            int j0 = wj*32 + mt*16 + lr;
            #pragma unroll
            for (int nt = 0; nt < 4; nt++) {
                int dl = wd*32 + nt*8 + lc;
                int col = h*HD + dl;
                float b0 = bq[col], b1 = bq[col+1];
                *(__half2*)(qs + j0*QS_S + dl) =
                    __floats2half2_rn(acc[mt][nt][0] + b0, acc[mt][nt][1] + b1);
                *(__half2*)(qs + (j0+8)*QS_S + dl) =
                    __floats2half2_rn(acc[mt][nt][2] + b0, acc[mt][nt][3] + b1);
            }
        }
    }
    CP_WAIT(1);          // B done (vw ready)
    __syncthreads();

    // -------- P1: score MMA on VW/qs --------
    {
        int iw = (wid >> 2)*32, jw = (wid & 3)*16;
        float acc[2][2][4] = {};
        #pragma unroll
        for (int ks = 0; ks < 16; ks++) {
            int k0 = ks*16;
            uint32_t a[2][4], bq2[2][2];
            #pragma unroll
            for (int mi = 0; mi < 2; mi++) {
                const __half* ab = VW + (iw + mi*16 + lr)*VW_S + k0 + lc;
                a[mi][0] = *(const uint32_t*)ab;
                a[mi][1] = *(const uint32_t*)(ab + 8*VW_S);
                a[mi][2] = *(const uint32_t*)(ab + 8);
                a[mi][3] = *(const uint32_t*)(ab + 8*VW_S + 8);
            }
            #pragma unroll
            for (int nj = 0; nj < 2; nj++) {
                const __half* bb = qs + (jw + nj*8 + lr)*QS_S + k0 + lc;
                bq2[nj][0] = *(const uint32_t*)bb;
                bq2[nj][1] = *(const uint32_t*)(bb + 8);
            }
            #pragma unroll
            for (int mi = 0; mi < 2; mi++)
                #pragma unroll
                for (int nj = 0; nj < 2; nj++)
                    mma16816(acc[mi][nj], a[mi], bq2[nj]);
        }
        #pragma unroll
        for (int mi = 0; mi < 2; mi++) {
            int i0 = iw + mi*16 + lr;
            #pragma unroll
            for (int nj = 0; nj < 2; nj++) {
                int j0 = jw + nj*8 + lc;
                sc[j0*SC_S + i0]       = acc[mi][nj][0];
                sc[(j0+1)*SC_S + i0]   = acc[mi][nj][1];
                sc[j0*SC_S + i0+8]     = acc[mi][nj][2];
                sc[(j0+1)*SC_S + i0+8] = acc[mi][nj][3];
            }
        }
    }
    __syncthreads();

    // -------- softmax over i --------
    #pragma unroll
    for (int rr = 0; rr < 4; rr++) {
        int j = wid*4 + rr;
        float4 x = *(float4*)(sc + j*SC_S + lane*4);
        float mx = fmaxf(fmaxf(x.x, x.y), fmaxf(x.z, x.w));
        #pragma unroll
        for (int off = 16; off; off >>= 1)
            mx = fmaxf(mx, __shfl_xor_sync(0xffffffffu, mx, off));
        float4 e;
        e.x = __expf(x.x - mx); e.y = __expf(x.y - mx);
        e.z = __expf(x.z - mx); e.w = __expf(x.w - mx);
        float s = e.x + e.y + e.z + e.w;
        #pragma unroll
        for (int off = 16; off; off >>= 1)
            s += __shfl_xor_sync(0xffffffffu, s, off);
        *(float4*)(sc + j*SC_S + lane*4) = e;
        *(__half2*)(ebf + j*EB_S + lane*4)     = __floats2half2_rn(e.x, e.y);
        *(__half2*)(ebf + j*EB_S + lane*4 + 2) = __floats2half2_rn(e.z, e.w);
        if (lane == 0) inv[j] = 1.0f / s;
    }
    __syncthreads();

    // -------- write att --------
    float* attp = att_out + ((size_t)(b*2 + h)*NV_)*NQ_ + jt*64;
    #pragma unroll
    for (int it = 0; it < 16; it++) {
        int e = it*512 + t;
        int i = e >> 6, j = e & 63;
        attp[(size_t)i*NQ_ + j] = sc[j*SC_S + i] * inv[j];
    }

    CP_WAIT(0);          // vT ready
    __syncthreads();

    float* ph = sc;
    if (t < 256) ph[t] = 0.f;
    __syncthreads();

    // -------- P2: MMA on ebf/X(vT); ph smem atomics --------
    {
        int jw2 = (wid >> 3)*32, dw = (wid & 7)*32;
        float acc[2][4][4] = {};
        #pragma unroll
        for (int ks = 0; ks < 8; ks++) {
            int k0 = ks*16;
            uint32_t a[2][4], bvv[4][2];
            #pragma unroll
            for (int mi = 0; mi < 2; mi++) {
                const __half* ab = ebf + (jw2 + mi*16 + lr)*EB_S + k0 + lc;
                a[mi][0] = *(const uint32_t*)ab;
                a[mi][1] = *(const uint32_t*)(ab + 8*EB_S);
                a[mi][2] = *(const uint32_t*)(ab + 8);
                a[mi][3] = *(const uint32_t*)(ab + 8*EB_S + 8);
            }
            #pragma unroll
            for (int nt = 0; nt < 4; nt++) {
                const __half* bb = X + (dw + nt*8 + lr)*VT_S + k0 + lc;
                bvv[nt][0] = *(const uint32_t*)bb;
                bvv[nt][1] = *(const uint32_t*)(bb + 8);
            }
            #pragma unroll
            for (int mi = 0; mi < 2; mi++)
                #pragma unroll
                for (int nt = 0; nt < 4; nt++)
                    mma16816(acc[mi][nt], a[mi], bvv[nt]);
        }
        #pragma unroll
        for (int nt = 0; nt < 4; nt++) {
            int d0 = dw + nt*8 + lc;
            float va = 0.f, vb = 0.f;
            #pragma unroll
            for (int mi = 0; mi < 2; mi++) {
                int j0 = jw2 + mi*16 + lr, j1 = j0 + 8;
                float w0 = inv[j0], w1 = inv[j1];
                float q00 = __half2float(qs[j0*QS_S + d0]);
                float q01 = __half2float(qs[j0*QS_S + d0+1]);
                float q10 = __half2float(qs[j1*QS_S + d0]);
                float q11 = __half2float(qs[j1*QS_S + d0+1]);
                va += acc[mi][nt][0]*w0*q00 + acc[mi][nt][2]*w1*q10;
                vb += acc[mi][nt][1]*w0*q01 + acc[mi][nt][3]*w1*q11;
            }
            va += __shfl_xor_sync(0xffffffffu, va, 4);
            va += __shfl_xor_sync(0xffffffffu, va, 8);
            va += __shfl_xor_sync(0xffffffffu, va, 16);
            vb += __shfl_xor_sync(0xffffffffu, vb, 4);
            vb += __shfl_xor_sync(0xffffffffu, vb, 8);
            vb += __shfl_xor_sync(0xffffffffu, vb, 16);
            if (lr == 0) {
                atomicAdd(ph + d0,     va);
                atomicAdd(ph + d0 + 1, vb);
            }
        }
    }
    __syncthreads();

    // -------- fused tail: out[b,:] += ph @ Wo[h*256:,:] (+ bo once) --------
    {
        int wd = wid >> 3;
        int wn = wid & 7;
        int n = wn*32 + lane;
        const float* wop = Wo + ((size_t)(h*HD + wd*128))*HD + n;
        const float* php = ph + wd*128;
        float f0 = 0.f, f1 = 0.f, f2 = 0.f, f3 = 0.f;
        #pragma unroll
        for (int d = 0; d < 128; d += 4) {
            f0 += php[d]   * wop[(size_t)(d  )*HD];
            f1 += php[d+1] * wop[(size_t)(d+1)*HD];
            f2 += php[d+2] * wop[(size_t)(d+2)*HD];
            f3 += php[d+3] * wop[(size_t)(d+3)*HD];
        }
        float f = (f0 + f1) + (f2 + f3);
        if (wd == 0 && (bid & 15) == 0) f += bo[n];
        atomicAdd(&out[b*HD + n], f);
    }
}

// ============================================================
extern "C" void kernel_launch(void* const* d_in, const int* in_sizes, int n_in,
                              void* d_out, int out_size)
{
    const float* v  = (const float*)d_in[0];
    const float* q  = (const float*)d_in[1];
    const float* Wv = (const float*)d_in[2];
    const float* bv = (const float*)d_in[3];
    const float* Wq = (const float*)d_in[4];
    const float* bq = (const float*)d_in[5];
    const float* wa = (const float*)d_in[6];
    // d_in[7] = ba : constant shift before softmax -> drops out
    const float* Wo = (const float*)d_in[8];
    const float* bo = (const float*)d_in[9];
    float* out = (float*)d_out;

    const int SSM = 222464;
    cudaFuncSetAttribute(ban_k, cudaFuncAttributeMaxDynamicSharedMemorySize, SSM);
    ban_k<<<NCTA, 512, SSM>>>(v, q, Wv, Wq, bv, bq, wa, Wo, bo, out);
}

// round 15
// speedup vs baseline: 1.0651x; 1.0651x over previous
#include <cuda_runtime.h>
#include <cuda_fp16.h>
#include <stdint.h>

#define B_    8
#define NV_   128
#define NQ_   512
#define DIN   128
#define DPROJ 512
#define HD    256

#define PR_S  136
#define VW_S  264
#define SC_S  130
#define EB_S  136
#define VT_S  136
#define QS_S  264

// ---- device scratch (allocations forbidden) ----
__device__ __half g_vw16[B_*NV_*DPROJ];   // v_*wa : [b*128+i][512]
__device__ __half g_vT16[B_*DPROJ*NV_];   // v_^T  : [b][512][128]
__device__ __half g_WqT [DPROJ*DIN];      // Wq^T f16 [512][128]

__device__ __forceinline__ void mma16816(float* c, const uint32_t* a, const uint32_t* b) {
    asm volatile(
        "mma.sync.aligned.m16n8k16.row.col.f32.f16.f16.f32 "
        "{%0,%1,%2,%3}, {%4,%5,%6,%7}, {%8,%9}, {%0,%1,%2,%3};\n"
        : "+f"(c[0]), "+f"(c[1]), "+f"(c[2]), "+f"(c[3])
        : "r"(a[0]), "r"(a[1]), "r"(a[2]), "r"(a[3]), "r"(b[0]), "r"(b[1]));
}

__device__ __forceinline__ void cp_async16(void* s, const void* g) {
    uint32_t sa = (uint32_t)__cvta_generic_to_shared(s);
    asm volatile("cp.async.cg.shared.global [%0], [%1], 16;" :: "r"(sa), "l"(g));
}
#define CP_COMMIT()  asm volatile("cp.async.commit_group;" ::: "memory")
#define CP_WAIT(n)   asm volatile("cp.async.wait_group %0;" :: "n"(n) : "memory")

// ============================================================
// prep: 48 CTAs, 512 thr.
//   bid < 32 : v-projection (Wv transposed inline, f16x2 stores)
//   bid >= 32: Wq transpose tile -> g_WqT ; bid==32 zeroes out
// ============================================================
__global__ __launch_bounds__(512) void prep_k(
    const float* __restrict__ v,  const float* __restrict__ Wv,
    const float* __restrict__ Wq, const float* __restrict__ bv,
    const float* __restrict__ wa, float* __restrict__ out)
{
    extern __shared__ __align__(16) char smem[];
    int t = threadIdx.x;
    int bid = blockIdx.x;

    if (bid >= 32) {
        __half* s = (__half*)smem;                 // [32][136]
        int n0 = (bid - 32) * 32;
        if (bid == 32) {
            #pragma unroll
            for (int it = 0; it < 4; it++) out[t + it*512] = 0.f;
        }
        #pragma unroll
        for (int it = 0; it < 8; it++) {
            int fi = t + it*512;
            int k = fi >> 5, nn = fi & 31;
            s[nn*136 + k] = __float2half(Wq[(size_t)k*DPROJ + n0 + nn]);
        }
        __syncthreads();
        {
            int n = t >> 4, kq = (t & 15)*8;
            *(float4*)(g_WqT + (size_t)(n0 + n)*DIN + kq) = *(const float4*)(s + n*136 + kq);
        }
        return;
    }

    __half* As = (__half*)smem;                    // [128][136]
    __half* Bs = (__half*)(smem + 128*PR_S*2);     // [128][136]

    int bn = (bid & 3) * 128;
    int my = bid >> 2;
    int bm = my * 128;

    #pragma unroll
    for (int it = 0; it < 8; it++) {
        int fi = t + it*512;
        int m = fi >> 5, k = (fi & 31)*4;
        float4 f = *(const float4*)(v + (size_t)(bm+m)*DIN + k);
        __half2 h0 = __floats2half2_rn(f.x, f.y);
        __half2 h1 = __floats2half2_rn(f.z, f.w);
        uint2 u; u.x = *(uint32_t*)&h0; u.y = *(uint32_t*)&h1;
        *(uint2*)(As + m*PR_S + k) = u;
    }
    // inline transpose of Wv: 2 k per thread -> f16x2 stores (4-way conflict)
    #pragma unroll
    for (int it = 0; it < 16; it++) {
        int fi = t + it*512;                       // 8192 pairs
        int k2 = fi >> 7, n = fi & 127;            // k2 0..63
        __half2 hv = __floats2half2_rn(
            Wv[(size_t)(2*k2  )*DPROJ + bn + n],
            Wv[(size_t)(2*k2+1)*DPROJ + bn + n]);
        *(__half2*)(Bs + n*PR_S + 2*k2) = hv;
    }
    __syncthreads();

    int lane = t & 31, wid = t >> 5;
    int warpM = wid >> 2, warpN = wid & 3;
    int lr = lane >> 2, lc = (lane & 3)*2;

    float acc[2][4][4] = {};
    #pragma unroll
    for (int ks = 0; ks < 8; ks++) {
        int k0 = ks*16;
        uint32_t a[2][4], b[4][2];
        #pragma unroll
        for (int mt = 0; mt < 2; mt++) {
            const __half* ab = As + (warpM*32 + mt*16 + lr)*PR_S + k0 + lc;
            a[mt][0] = *(const uint32_t*)ab;
            a[mt][1] = *(const uint32_t*)(ab + 8*PR_S);
            a[mt][2] = *(const uint32_t*)(ab + 8);
            a[mt][3] = *(const uint32_t*)(ab + 8*PR_S + 8);
        }
        #pragma unroll
        for (int nt = 0; nt < 4; nt++) {
            const __half* bb = Bs + (warpN*32 + nt*8 + lr)*PR_S + k0 + lc;
            b[nt][0] = *(const uint32_t*)bb;
            b[nt][1] = *(const uint32_t*)(bb + 8);
        }
        #pragma unroll
        for (int mt = 0; mt < 2; mt++)
            #pragma unroll
            for (int nt = 0; nt < 4; nt++)
                mma16816(acc[mt][nt], a[mt], b[nt]);
    }
    __syncthreads();

    #pragma unroll
    for (int mt = 0; mt < 2; mt++) {
        int rowL = warpM*32 + mt*16 + lr;
        #pragma unroll
        for (int nt = 0; nt < 4; nt++) {
            int colL = warpN*32 + nt*8 + lc;
            int col = bn + colL;
            float b0 = bv[col], b1 = bv[col+1];
            float v00 = acc[mt][nt][0] + b0, v01 = acc[mt][nt][1] + b1;
            float v10 = acc[mt][nt][2] + b0, v11 = acc[mt][nt][3] + b1;
            int row = bm + rowL;
            float w0 = wa[col & 255], w1 = wa[(col+1) & 255];
            *(__half2*)(g_vw16 + (size_t)row*DPROJ + col) =
                __floats2half2_rn(v00*w0, v01*w1);
            *(__half2*)(g_vw16 + (size_t)(row+8)*DPROJ + col) =
                __floats2half2_rn(v10*w0, v11*w1);
            __half* tr = As;
            tr[colL*PR_S + rowL]       = __float2half(v00);
            tr[(colL+1)*PR_S + rowL]   = __float2half(v01);
            tr[colL*PR_S + rowL+8]     = __float2half(v10);
            tr[(colL+1)*PR_S + rowL+8] = __float2half(v11);
        }
    }
    __syncthreads();
    const __half* tr = As;
    #pragma unroll
    for (int it = 0; it < 4; it++) {
        int fi = t + it*512;
        int n = fi >> 4, k = (fi & 15)*8;
        *(float4*)(g_vT16 + ((size_t)my*DPROJ + bn + n)*NV_ + k) =
            *(const float4*)(tr + n*PR_S + k);
    }
}

// ============================================================
// Score kernel (R13) — sc stride 130 (2-way att-read conflicts).
// ============================================================
__global__ __launch_bounds__(512) void score_k(
    const float* __restrict__ q,  const float* __restrict__ bq,
    const float* __restrict__ Wo, const float* __restrict__ bo,
    float* __restrict__ out)
{
    extern __shared__ __align__(16) char smem[];
    __half* X   = (__half*)smem;                  // WqT [256][136] -> vT [256][136]
    __half* VW  = (__half*)(smem + 69632);        // vw [128][264]
    __half* qs  = (__half*)(smem + 137216);       // [64][264]
    float*  sc  = (float*) (smem + 171008);       // [64][130] ; later ph[256]
    __half* ebf = (__half*)(smem + 204800);       // q-in [64][136] / exp [64][136]
    float*  inv = (float*) (smem + 222208);       // [64]

    int t = threadIdx.x;
    int bid = blockIdx.x;
    int jt = bid & 7, h = (bid >> 3) & 1, b = bid >> 4;
    int lane = t & 31, wid = t >> 5;
    int lr = lane >> 2, lc = (lane & 3)*2;
    float* att_out = out + B_*HD;

    // ---- issue async loads: WqT (group A), vw (group B) ----
    {
        const __half* wqt = g_WqT + (size_t)(h*HD)*DIN;
        #pragma unroll
        for (int it = 0; it < 8; it++) {
            int fi = t + it*512;
            int n = fi >> 4, k = (fi & 15)*8;
            cp_async16(X + n*PR_S + k, wqt + (size_t)n*DIN + k);
        }
        CP_COMMIT();   // group A
        const __half* vwg = g_vw16 + ((size_t)b*NV_)*DPROJ + h*HD;
        #pragma unroll
        for (int it = 0; it < 8; it++) {
            int fi = t + it*512;
            int i = fi >> 5, k = (fi & 31)*8;
            cp_async16(VW + i*VW_S + k, vwg + (size_t)i*DPROJ + k);
        }
        CP_COMMIT();   // group B
    }

    // ---- regular load + convert q-in ----
    {
        __half* qin = ebf;
        #pragma unroll
        for (int it = 0; it < 4; it++) {
            int fi = t + it*512;
            int m = fi >> 5, k = (fi & 31)*4;
            float4 f = *(const float4*)(q + (size_t)(b*NQ_ + jt*64 + m)*DIN + k);
            __half2 h0 = __floats2half2_rn(f.x, f.y);
            __half2 h1 = __floats2half2_rn(f.z, f.w);
            uint2 u; u.x = *(uint32_t*)&h0; u.y = *(uint32_t*)&h1;
            *(uint2*)(qin + m*PR_S + k) = u;
        }
    }
    CP_WAIT(1);
    __syncthreads();

    // -------- P0: q projection --------
    {
        __half* qin = ebf;
        int wj = wid >> 3, wd = wid & 7;
        float acc[2][4][4] = {};
        #pragma unroll
        for (int ks = 0; ks < 8; ks++) {
            int k0 = ks*16;
            uint32_t a[2][4], bb2[4][2];
            #pragma unroll
            for (int mt = 0; mt < 2; mt++) {
                const __half* ab = qin + (wj*32 + mt*16 + lr)*PR_S + k0 + lc;
                a[mt][0] = *(const uint32_t*)ab;
                a[mt][1] = *(const uint32_t*)(ab + 8*PR_S);
                a[mt][2] = *(const uint32_t*)(ab + 8);
                a[mt][3] = *(const uint32_t*)(ab + 8*PR_S + 8);
            }
            #pragma unroll
            for (int nt = 0; nt < 4; nt++) {
                const __half* bb = X + (wd*32 + nt*8 + lr)*PR_S + k0 + lc;
                bb2[nt][0] = *(const uint32_t*)bb;
                bb2[nt][1] = *(const uint32_t*)(bb + 8);
            }
            #pragma unroll
            for (int mt = 0; mt < 2; mt++)
                #pragma unroll
                for (int nt = 0; nt < 4; nt++)
                    mma16816(acc[mt][nt], a[mt], bb2[nt]);
        }
        __syncthreads();

        // ---- issue vT async into X (group C) ----
        {
            const __half* vtg = g_vT16 + ((size_t)b*DPROJ + h*HD)*NV_;
            #pragma unroll
            for (int it = 0; it < 8; it++) {
                int fi = t + it*512;
                int d = fi >> 4, k = (fi & 15)*8;
                cp_async16(X + d*VT_S + k, vtg + (size_t)d*NV_ + k);
            }
            CP_COMMIT();   // group C
        }

        #pragma unroll
        for (int mt = 0; mt < 2; mt++) {
            int j0 = wj*32 + mt*16 + lr;
            #pragma unroll
            for (int nt = 0; nt < 4; nt++) {
                int dl = wd*32 + nt*8 + lc;
                int col = h*HD + dl;
                float b0 = bq[col], b1 = bq[col+1];
                *(__half2*)(qs + j0*QS_S + dl) =
                    __floats2half2_rn(acc[mt][nt][0] + b0, acc[mt][nt][1] + b1);
                *(__half2*)(qs + (j0+8)*QS_S + dl) =
                    __floats2half2_rn(acc[mt][nt][2] + b0, acc[mt][nt][3] + b1);
            }
        }
    }
    CP_WAIT(1);
    __syncthreads();

    // -------- P1: score MMA --------
    {
        int iw = (wid >> 2)*32, jw = (wid & 3)*16;
        float acc[2][2][4] = {};
        #pragma unroll
        for (int ks = 0; ks < 16; ks++) {
            int k0 = ks*16;
            uint32_t a[2][4], bq2[2][2];
            #pragma unroll
            for (int mi = 0; mi < 2; mi++) {
                const __half* ab = VW + (iw + mi*16 + lr)*VW_S + k0 + lc;
                a[mi][0] = *(const uint32_t*)ab;
                a[mi][1] = *(const uint32_t*)(ab + 8*VW_S);
                a[mi][2] = *(const uint32_t*)(ab + 8);
                a[mi][3] = *(const uint32_t*)(ab + 8*VW_S + 8);
            }
            #pragma unroll
            for (int nj = 0; nj < 2; nj++) {
                const __half* bb = qs + (jw + nj*8 + lr)*QS_S + k0 + lc;
                bq2[nj][0] = *(const uint32_t*)bb;
                bq2[nj][1] = *(const uint32_t*)(bb + 8);
            }
            #pragma unroll
            for (int mi = 0; mi < 2; mi++)
                #pragma unroll
                for (int nj = 0; nj < 2; nj++)
                    mma16816(acc[mi][nj], a[mi], bq2[nj]);
        }
        #pragma unroll
        for (int mi = 0; mi < 2; mi++) {
            int i0 = iw + mi*16 + lr;
            #pragma unroll
            for (int nj = 0; nj < 2; nj++) {
                int j0 = jw + nj*8 + lc;
                sc[j0*SC_S + i0]       = acc[mi][nj][0];
                sc[(j0+1)*SC_S + i0]   = acc[mi][nj][1];
                sc[j0*SC_S + i0+8]     = acc[mi][nj][2];
                sc[(j0+1)*SC_S + i0+8] = acc[mi][nj][3];
            }
        }
    }
    __syncthreads();

    // -------- softmax over i (float2 reads: SC_S=130) --------
    #pragma unroll
    for (int rr = 0; rr < 4; rr++) {
        int j = wid*4 + rr;
        float2 x01 = *(float2*)(sc + j*SC_S + lane*4);
        float2 x23 = *(float2*)(sc + j*SC_S + lane*4 + 2);
        float mx = fmaxf(fmaxf(x01.x, x01.y), fmaxf(x23.x, x23.y));
        #pragma unroll
        for (int off = 16; off; off >>= 1)
            mx = fmaxf(mx, __shfl_xor_sync(0xffffffffu, mx, off));
        float e0 = __expf(x01.x - mx), e1 = __expf(x01.y - mx);
        float e2 = __expf(x23.x - mx), e3 = __expf(x23.y - mx);
        float s = e0 + e1 + e2 + e3;
        #pragma unroll
        for (int off = 16; off; off >>= 1)
            s += __shfl_xor_sync(0xffffffffu, s, off);
        float2 w01; w01.x = e0; w01.y = e1;
        float2 w23; w23.x = e2; w23.y = e3;
        *(float2*)(sc + j*SC_S + lane*4)     = w01;
        *(float2*)(sc + j*SC_S + lane*4 + 2) = w23;
        *(__half2*)(ebf + j*EB_S + lane*4)     = __floats2half2_rn(e0, e1);
        *(__half2*)(ebf + j*EB_S + lane*4 + 2) = __floats2half2_rn(e2, e3);
        if (lane == 0) inv[j] = 1.0f / s;
    }
    __syncthreads();

    // -------- write att --------
    float* attp = att_out + ((size_t)(b*2 + h)*NV_)*NQ_ + jt*64;
    #pragma unroll
    for (int it = 0; it < 16; it++) {
        int e = it*512 + t;
        int i = e >> 6, j = e & 63;
        attp[(size_t)i*NQ_ + j] = sc[j*SC_S + i] * inv[j];
    }

    CP_WAIT(0);
    __syncthreads();

    float* ph = sc;
    if (t < 256) ph[t] = 0.f;
    __syncthreads();

    // -------- P2: MMA on ebf/X(vT); ph smem atomics --------
    {
        int jw2 = (wid >> 3)*32, dw = (wid & 7)*32;
        float acc[2][4][4] = {};
        #pragma unroll
        for (int ks = 0; ks < 8; ks++) {
            int k0 = ks*16;
            uint32_t a[2][4], bvv[4][2];
            #pragma unroll
            for (int mi = 0; mi < 2; mi++) {
                const __half* ab = ebf + (jw2 + mi*16 + lr)*EB_S + k0 + lc;
                a[mi][0] = *(const uint32_t*)ab;
                a[mi][1] = *(const uint32_t*)(ab + 8*EB_S);
                a[mi][2] = *(const uint32_t*)(ab + 8);
                a[mi][3] = *(const uint32_t*)(ab + 8*EB_S + 8);
            }
            #pragma unroll
            for (int nt = 0; nt < 4; nt++) {
                const __half* bb = X + (dw + nt*8 + lr)*VT_S + k0 + lc;
                bvv[nt][0] = *(const uint32_t*)bb;
                bvv[nt][1] = *(const uint32_t*)(bb + 8);
            }
            #pragma unroll
            for (int mi = 0; mi < 2; mi++)
                #pragma unroll
                for (int nt = 0; nt < 4; nt++)
                    mma16816(acc[mi][nt], a[mi], bvv[nt]);
        }
        #pragma unroll
        for (int nt = 0; nt < 4; nt++) {
            int d0 = dw + nt*8 + lc;
            float va = 0.f, vb = 0.f;
            #pragma unroll
            for (int mi = 0; mi < 2; mi++) {
                int j0 = jw2 + mi*16 + lr, j1 = j0 + 8;
                float w0 = inv[j0], w1 = inv[j1];
                float q00 = __half2float(qs[j0*QS_S + d0]);
                float q01 = __half2float(qs[j0*QS_S + d0+1]);
                float q10 = __half2float(qs[j1*QS_S + d0]);
                float q11 = __half2float(qs[j1*QS_S + d0+1]);
                va += acc[mi][nt][0]*w0*q00 + acc[mi][nt][2]*w1*q10;
                vb += acc[mi][nt][1]*w0*q01 + acc[mi][nt][3]*w1*q11;
            }
            va += __shfl_xor_sync(0xffffffffu, va, 4);
            va += __shfl_xor_sync(0xffffffffu, va, 8);
            va += __shfl_xor_sync(0xffffffffu, va, 16);
            vb += __shfl_xor_sync(0xffffffffu, vb, 4);
            vb += __shfl_xor_sync(0xffffffffu, vb, 8);
            vb += __shfl_xor_sync(0xffffffffu, vb, 16);
            if (lr == 0) {
                atomicAdd(ph + d0,     va);
                atomicAdd(ph + d0 + 1, vb);
            }
        }
    }
    __syncthreads();

    // -------- fused tail: out[b,:] += ph @ Wo[h*256:,:] (+ bo once) --------
    {
        int wd = wid >> 3;
        int wn = wid & 7;
        int n = wn*32 + lane;
        const float* wop = Wo + ((size_t)(h*HD + wd*128))*HD + n;
        const float* php = ph + wd*128;
        float f0 = 0.f, f1 = 0.f, f2 = 0.f, f3 = 0.f;
        #pragma unroll
        for (int d = 0; d < 128; d += 4) {
            f0 += php[d]   * wop[(size_t)(d  )*HD];
            f1 += php[d+1] * wop[(size_t)(d+1)*HD];
            f2 += php[d+2] * wop[(size_t)(d+2)*HD];
            f3 += php[d+3] * wop[(size_t)(d+3)*HD];
        }
        float f = (f0 + f1) + (f2 + f3);
        if (wd == 0 && (bid & 15) == 0) f += bo[n];
        atomicAdd(&out[b*HD + n], f);
    }
}

// ============================================================
extern "C" void kernel_launch(void* const* d_in, const int* in_sizes, int n_in,
                              void* d_out, int out_size)
{
    const float* v  = (const float*)d_in[0];
    const float* q  = (const float*)d_in[1];
    const float* Wv = (const float*)d_in[2];
    const float* bv = (const float*)d_in[3];
    const float* Wq = (const float*)d_in[4];
    const float* bq = (const float*)d_in[5];
    const float* wa = (const float*)d_in[6];
    // d_in[7] = ba : constant shift before softmax -> drops out
    const float* Wo = (const float*)d_in[8];
    const float* bo = (const float*)d_in[9];
    float* out = (float*)d_out;

    const int PSM = 2 * 128 * PR_S * 2;   // 69632 B
    const int SSM = 222464;
    cudaFuncSetAttribute(prep_k,  cudaFuncAttributeMaxDynamicSharedMemorySize, PSM);
    cudaFuncSetAttribute(score_k, cudaFuncAttributeMaxDynamicSharedMemorySize, SSM);

    prep_k<<<48, 512, PSM>>>(v, Wv, Wq, bv, wa, out);
    score_k<<<128, 512, SSM>>>(q, bq, Wo, bo, out);
}

// round 16
// speedup vs baseline: 1.0665x; 1.0013x over previous
#include <cuda_runtime.h>
#include <cuda_fp16.h>
#include <stdint.h>

#define B_    8
#define NV_   128
#define NQ_   512
#define DIN   128
#define DPROJ 512
#define HD    256

#define PR_S  136
#define VW_S  264
#define SC_S  130
#define EB_S  136
#define VT_S  136
#define QS_S  264

#define NCTA  128

// ---- device scratch (allocations forbidden) ----
__device__ __half g_vw16[B_*NV_*DPROJ];   // v_*wa : [b*128+i][512]
__device__ __half g_vT16[B_*DPROJ*NV_];   // v_^T  : [b][512][128]
__device__ __half g_WqT [DPROJ*DIN];      // Wq^T f16 [512][128]
__device__ unsigned g_ep;                 // monotonic CTA ticket (epoch = /128)
__device__ unsigned g_flagV[B_];          // vproj done counters (4 per b per replay)
__device__ unsigned g_flagW;              // WqT done counter (16 per replay)

__device__ __forceinline__ void mma16816(float* c, const uint32_t* a, const uint32_t* b) {
    asm volatile(
        "mma.sync.aligned.m16n8k16.row.col.f32.f16.f16.f32 "
        "{%0,%1,%2,%3}, {%4,%5,%6,%7}, {%8,%9}, {%0,%1,%2,%3};\n"
        : "+f"(c[0]), "+f"(c[1]), "+f"(c[2]), "+f"(c[3])
        : "r"(a[0]), "r"(a[1]), "r"(a[2]), "r"(a[3]), "r"(b[0]), "r"(b[1]));
}

__device__ __forceinline__ void cp_async16(void* s, const void* g) {
    uint32_t sa = (uint32_t)__cvta_generic_to_shared(s);
    asm volatile("cp.async.cg.shared.global [%0], [%1], 16;" :: "r"(sa), "l"(g));
}
#define CP_COMMIT()  asm volatile("cp.async.commit_group;" ::: "memory")
#define CP_WAIT(n)   asm volatile("cp.async.wait_group %0;" :: "n"(n) : "memory")

__device__ __forceinline__ void wait_ge(unsigned* p, unsigned tgt) {
    unsigned cur;
    do {
        asm volatile("ld.acquire.gpu.u32 %0, [%1];" : "=r"(cur) : "l"(p));
    } while (cur < tgt);
}

// ============================================================
// Single fused kernel: 128 CTAs x 512 thr, 222.5KB smem (all resident).
// Duty phase (flag-signaled, no global barrier):
//   bid<32: vproj (inline Wv transpose) -> g_vw16/g_vT16, flagV[b]+=1
//   bid 32-47: WqT transpose (+bid 32 zeroes out-fused), flagW+=1
// Score phase: all CTAs, per (jt,h,b), with cp.async pipeline; waits on
//   flagW before WqT fetch, flagV[b] before vw fetch.
// ============================================================
__global__ __launch_bounds__(512, 1) void ban_k(
    const float* __restrict__ v,  const float* __restrict__ q,
    const float* __restrict__ Wv, const float* __restrict__ Wq,
    const float* __restrict__ bv, const float* __restrict__ bq,
    const float* __restrict__ wa, const float* __restrict__ Wo,
    const float* __restrict__ bo, float* __restrict__ out)
{
    extern __shared__ __align__(16) char smem[];
    __half* X   = (__half*)smem;                  // duty As ; score WqT -> vT [256][136]
    __half* VW  = (__half*)(smem + 69632);        // duty Bs/stage ; score vw [128][264]
    __half* qs  = (__half*)(smem + 137216);       // [64][264]
    float*  sc  = (float*) (smem + 171008);       // [64][130] ; later ph[256]
    __half* ebf = (__half*)(smem + 204800);       // q-in [64][136] -> exp [64][136]
    float*  inv = (float*) (smem + 222208);       // [64]

    int t = threadIdx.x;
    int bid = blockIdx.x;
    int jt = bid & 7, h = (bid >> 3) & 1, b = bid >> 4;
    int lane = t & 31, wid = t >> 5;
    int lr = lane >> 2, lc = (lane & 3)*2;
    float* att_out = out + B_*HD;

    unsigned epoch = 0;
    if (t == 0) epoch = atomicAdd(&g_ep, 1u) >> 7;   // replay index

    // ================= duty phase =================
    if (bid < 32) {
        // ---- vproj ----
        __half* As = X;                            // [128][136]
        __half* Bs = VW;                           // [128][136]
        int bn = (bid & 3) * 128;
        int my = bid >> 2;
        int bm = my * 128;

        #pragma unroll
        for (int it = 0; it < 8; it++) {
            int fi = t + it*512;
            int m = fi >> 5, k = (fi & 31)*4;
            float4 f = *(const float4*)(v + (size_t)(bm+m)*DIN + k);
            __half2 h0 = __floats2half2_rn(f.x, f.y);
            __half2 h1 = __floats2half2_rn(f.z, f.w);
            uint2 u; u.x = *(uint32_t*)&h0; u.y = *(uint32_t*)&h1;
            *(uint2*)(As + m*PR_S + k) = u;
        }
        #pragma unroll
        for (int it = 0; it < 16; it++) {
            int fi = t + it*512;                   // 8192 k-pairs
            int k2 = fi >> 7, n = fi & 127;
            __half2 hv = __floats2half2_rn(
                Wv[(size_t)(2*k2  )*DPROJ + bn + n],
                Wv[(size_t)(2*k2+1)*DPROJ + bn + n]);
            *(__half2*)(Bs + n*PR_S + 2*k2) = hv;
        }
        __syncthreads();

        int warpM = wid >> 2, warpN = wid & 3;
        float acc[2][4][4] = {};
        #pragma unroll
        for (int ks = 0; ks < 8; ks++) {
            int k0 = ks*16;
            uint32_t a[2][4], bb[4][2];
            #pragma unroll
            for (int mt = 0; mt < 2; mt++) {
                const __half* ab = As + (warpM*32 + mt*16 + lr)*PR_S + k0 + lc;
                a[mt][0] = *(const uint32_t*)ab;
                a[mt][1] = *(const uint32_t*)(ab + 8*PR_S);
                a[mt][2] = *(const uint32_t*)(ab + 8);
                a[mt][3] = *(const uint32_t*)(ab + 8*PR_S + 8);
            }
            #pragma unroll
            for (int nt = 0; nt < 4; nt++) {
                const __half* bp = Bs + (warpN*32 + nt*8 + lr)*PR_S + k0 + lc;
                bb[nt][0] = *(const uint32_t*)bp;
                bb[nt][1] = *(const uint32_t*)(bp + 8);
            }
            #pragma unroll
            for (int mt = 0; mt < 2; mt++)
                #pragma unroll
                for (int nt = 0; nt < 4; nt++)
                    mma16816(acc[mt][nt], a[mt], bb[nt]);
        }
        __syncthreads();   // As reused as transpose staging

        #pragma unroll
        for (int mt = 0; mt < 2; mt++) {
            int rowL = warpM*32 + mt*16 + lr;
            #pragma unroll
            for (int nt = 0; nt < 4; nt++) {
                int colL = warpN*32 + nt*8 + lc;
                int col = bn + colL;
                float b0 = bv[col], b1 = bv[col+1];
                float v00 = acc[mt][nt][0] + b0, v01 = acc[mt][nt][1] + b1;
                float v10 = acc[mt][nt][2] + b0, v11 = acc[mt][nt][3] + b1;
                int row = bm + rowL;
                float w0 = wa[col & 255], w1 = wa[(col+1) & 255];
                *(__half2*)(g_vw16 + (size_t)row*DPROJ + col) =
                    __floats2half2_rn(v00*w0, v01*w1);
                *(__half2*)(g_vw16 + (size_t)(row+8)*DPROJ + col) =
                    __floats2half2_rn(v10*w0, v11*w1);
                __half* tr = As;
                tr[colL*PR_S + rowL]       = __float2half(v00);
                tr[(colL+1)*PR_S + rowL]   = __float2half(v01);
                tr[colL*PR_S + rowL+8]     = __float2half(v10);
                tr[(colL+1)*PR_S + rowL+8] = __float2half(v11);
            }
        }
        __syncthreads();
        const __half* tr = As;
        #pragma unroll
        for (int it = 0; it < 4; it++) {
            int fi = t + it*512;
            int n = fi >> 4, k = (fi & 15)*8;
            *(float4*)(g_vT16 + ((size_t)my*DPROJ + bn + n)*NV_ + k) =
                *(const float4*)(tr + n*PR_S + k);
        }
        __threadfence();
        __syncthreads();
        if (t == 0) atomicAdd(&g_flagV[my], 1u);
    } else if (bid < 48) {
        // ---- WqT transpose (+ zero out-fused on bid 32) ----
        __half* s = VW;                            // [32][136]
        int n0 = (bid - 32) * 32;
        if (bid == 32) {
            #pragma unroll
            for (int it = 0; it < 4; it++) out[t + it*512] = 0.f;
        }
        #pragma unroll
        for (int it = 0; it < 8; it++) {
            int fi = t + it*512;
            int k = fi >> 5, nn = fi & 31;
            s[nn*136 + k] = __float2half(Wq[(size_t)k*DPROJ + n0 + nn]);
        }
        __syncthreads();
        {
            int n = t >> 4, kq = (t & 15)*8;
            *(float4*)(g_WqT + (size_t)(n0 + n)*DIN + kq) = *(const float4*)(s + n*136 + kq);
        }
        __threadfence();
        __syncthreads();
        if (t == 0) atomicAdd(&g_flagW, 1u);
    }

    // ================= score phase =================
    // q-in load first (independent of producers; overlaps their duty)
    {
        __half* qin = ebf;
        #pragma unroll
        for (int it = 0; it < 4; it++) {
            int fi = t + it*512;
            int m = fi >> 5, k = (fi & 31)*4;
            float4 f = *(const float4*)(q + (size_t)(b*NQ_ + jt*64 + m)*DIN + k);
            __half2 h0 = __floats2half2_rn(f.x, f.y);
            __half2 h1 = __floats2half2_rn(f.z, f.w);
            uint2 u; u.x = *(uint32_t*)&h0; u.y = *(uint32_t*)&h1;
            *(uint2*)(qin + m*PR_S + k) = u;
        }
    }

    // wait WqT ready, then fetch it (group A)
    if (t == 0) wait_ge(&g_flagW, (epoch + 1u) * 16u);
    __syncthreads();
    {
        const __half* wqt = g_WqT + (size_t)(h*HD)*DIN;
        #pragma unroll
        for (int it = 0; it < 8; it++) {
            int fi = t + it*512;
            int n = fi >> 4, k = (fi & 15)*8;
            cp_async16(X + n*PR_S + k, wqt + (size_t)n*DIN + k);
        }
        CP_COMMIT();   // group A
    }
    // wait this batch's vproj, then fetch vw (group B)
    if (t == 0) wait_ge(&g_flagV[b], (epoch + 1u) * 4u);
    __syncthreads();
    {
        const __half* vwg = g_vw16 + ((size_t)b*NV_)*DPROJ + h*HD;
        #pragma unroll
        for (int it = 0; it < 8; it++) {
            int fi = t + it*512;
            int i = fi >> 5, k = (fi & 31)*8;
            cp_async16(VW + i*VW_S + k, vwg + (size_t)i*DPROJ + k);
        }
        CP_COMMIT();   // group B
    }
    CP_WAIT(1);        // A done
    __syncthreads();

    // -------- P0: q projection --------
    {
        __half* qin = ebf;
        int wj = wid >> 3, wd = wid & 7;
        float acc[2][4][4] = {};
        #pragma unroll
        for (int ks = 0; ks < 8; ks++) {
            int k0 = ks*16;
            uint32_t a[2][4], bb2[4][2];
            #pragma unroll
            for (int mt = 0; mt < 2; mt++) {
                const __half* ab = qin + (wj*32 + mt*16 + lr)*PR_S + k0 + lc;
                a[mt][0] = *(const uint32_t*)ab;
                a[mt][1] = *(const uint32_t*)(ab + 8*PR_S);
                a[mt][2] = *(const uint32_t*)(ab + 8);
                a[mt][3] = *(const uint32_t*)(ab + 8*PR_S + 8);
            }
            #pragma unroll
            for (int nt = 0; nt < 4; nt++) {
                const __half* bb = X + (wd*32 + nt*8 + lr)*PR_S + k0 + lc;
                bb2[nt][0] = *(const uint32_t*)bb;
                bb2[nt][1] = *(const uint32_t*)(bb + 8);
            }
            #pragma unroll
            for (int mt = 0; mt < 2; mt++)
                #pragma unroll
                for (int nt = 0; nt < 4; nt++)
                    mma16816(acc[mt][nt], a[mt], bb2[nt]);
        }
        __syncthreads();   // done reading X (WqT) and qin

        // ---- issue vT async into X (group C) ----
        {
            const __half* vtg = g_vT16 + ((size_t)b*DPROJ + h*HD)*NV_;
            #pragma unroll
            for (int it = 0; it < 8; it++) {
                int fi = t + it*512;
                int d = fi >> 4, k = (fi & 15)*8;
                cp_async16(X + d*VT_S + k, vtg + (size_t)d*NV_ + k);
            }
            CP_COMMIT();   // group C
        }

        #pragma unroll
        for (int mt = 0; mt < 2; mt++) {
            int j0 = wj*32 + mt*16 + lr;
            #pragma unroll
            for (int nt = 0; nt < 4; nt++) {
                int dl = wd*32 + nt*8 + lc;
                int col = h*HD + dl;
                float b0 = bq[col], b1 = bq[col+1];
                *(__half2*)(qs + j0*QS_S + dl) =
                    __floats2half2_rn(acc[mt][nt][0] + b0, acc[mt][nt][1] + b1);
                *(__half2*)(qs + (j0+8)*QS_S + dl) =
                    __floats2half2_rn(acc[mt][nt][2] + b0, acc[mt][nt][3] + b1);
            }
        }
    }
    CP_WAIT(1);        // B done (vw ready)
    __syncthreads();

    // -------- P1: score MMA --------
    {
        int iw = (wid >> 2)*32, jw = (wid & 3)*16;
        float acc[2][2][4] = {};
        #pragma unroll
        for (int ks = 0; ks < 16; ks++) {
            int k0 = ks*16;
            uint32_t a[2][4], bq2[2][2];
            #pragma unroll
            for (int mi = 0; mi < 2; mi++) {
                const __half* ab = VW + (iw + mi*16 + lr)*VW_S + k0 + lc;
                a[mi][0] = *(const uint32_t*)ab;
                a[mi][1] = *(const uint32_t*)(ab + 8*VW_S);
                a[mi][2] = *(const uint32_t*)(ab + 8);
                a[mi][3] = *(const uint32_t*)(ab + 8*VW_S + 8);
            }
            #pragma unroll
            for (int nj = 0; nj < 2; nj++) {
                const __half* bb = qs + (jw + nj*8 + lr)*QS_S + k0 + lc;
                bq2[nj][0] = *(const uint32_t*)bb;
                bq2[nj][1] = *(const uint32_t*)(bb + 8);
            }
            #pragma unroll
            for (int mi = 0; mi < 2; mi++)
                #pragma unroll
                for (int nj = 0; nj < 2; nj++)
                    mma16816(acc[mi][nj], a[mi], bq2[nj]);
        }
        #pragma unroll
        for (int mi = 0; mi < 2; mi++) {
            int i0 = iw + mi*16 + lr;
            #pragma unroll
            for (int nj = 0; nj < 2; nj++) {
                int j0 = jw + nj*8 + lc;
                sc[j0*SC_S + i0]       = acc[mi][nj][0];
                sc[(j0+1)*SC_S + i0]   = acc[mi][nj][1];
                sc[j0*SC_S + i0+8]     = acc[mi][nj][2];
                sc[(j0+1)*SC_S + i0+8] = acc[mi][nj][3];
            }
        }
    }
    __syncthreads();

    // -------- softmax over i --------
    #pragma unroll
    for (int rr = 0; rr < 4; rr++) {
        int j = wid*4 + rr;
        float2 x01 = *(float2*)(sc + j*SC_S + lane*4);
        float2 x23 = *(float2*)(sc + j*SC_S + lane*4 + 2);
        float mx = fmaxf(fmaxf(x01.x, x01.y), fmaxf(x23.x, x23.y));
        #pragma unroll
        for (int off = 16; off; off >>= 1)
            mx = fmaxf(mx, __shfl_xor_sync(0xffffffffu, mx, off));
        float e0 = __expf(x01.x - mx), e1 = __expf(x01.y - mx);
        float e2 = __expf(x23.x - mx), e3 = __expf(x23.y - mx);
        float s = e0 + e1 + e2 + e3;
        #pragma unroll
        for (int off = 16; off; off >>= 1)
            s += __shfl_xor_sync(0xffffffffu, s, off);
        float2 w01; w01.x = e0; w01.y = e1;
        float2 w23; w23.x = e2; w23.y = e3;
        *(float2*)(sc + j*SC_S + lane*4)     = w01;
        *(float2*)(sc + j*SC_S + lane*4 + 2) = w23;
        *(__half2*)(ebf + j*EB_S + lane*4)     = __floats2half2_rn(e0, e1);
        *(__half2*)(ebf + j*EB_S + lane*4 + 2) = __floats2half2_rn(e2, e3);
        if (lane == 0) inv[j] = 1.0f / s;
    }
    __syncthreads();

    // -------- write att --------
    float* attp = att_out + ((size_t)(b*2 + h)*NV_)*NQ_ + jt*64;
    #pragma unroll
    for (int it = 0; it < 16; it++) {
        int e = it*512 + t;
        int i = e >> 6, j = e & 63;
        attp[(size_t)i*NQ_ + j] = sc[j*SC_S + i] * inv[j];
    }

    CP_WAIT(0);        // vT ready
    __syncthreads();

    float* ph = sc;
    if (t < 256) ph[t] = 0.f;
    __syncthreads();

    // -------- P2: MMA on ebf/X(vT); ph smem atomics --------
    {
        int jw2 = (wid >> 3)*32, dw = (wid & 7)*32;
        float acc[2][4][4] = {};
        #pragma unroll
        for (int ks = 0; ks < 8; ks++) {
            int k0 = ks*16;
            uint32_t a[2][4], bvv[4][2];
            #pragma unroll
            for (int mi = 0; mi < 2; mi++) {
                const __half* ab = ebf + (jw2 + mi*16 + lr)*EB_S + k0 + lc;
                a[mi][0] = *(const uint32_t*)ab;
                a[mi][1] = *(const uint32_t*)(ab + 8*EB_S);
                a[mi][2] = *(const uint32_t*)(ab + 8);
                a[mi][3] = *(const uint32_t*)(ab + 8*EB_S + 8);
            }
            #pragma unroll
            for (int nt = 0; nt < 4; nt++) {
                const __half* bb = X + (dw + nt*8 + lr)*VT_S + k0 + lc;
                bvv[nt][0] = *(const uint32_t*)bb;
                bvv[nt][1] = *(const uint32_t*)(bb + 8);
            }
            #pragma unroll
            for (int mi = 0; mi < 2; mi++)
                #pragma unroll
                for (int nt = 0; nt < 4; nt++)
                    mma16816(acc[mi][nt], a[mi], bvv[nt]);
        }
        #pragma unroll
        for (int nt = 0; nt < 4; nt++) {
            int d0 = dw + nt*8 + lc;
            float va = 0.f, vb = 0.f;
            #pragma unroll
            for (int mi = 0; mi < 2; mi++) {
                int j0 = jw2 + mi*16 + lr, j1 = j0 + 8;
                float w0 = inv[j0], w1 = inv[j1];
                float q00 = __half2float(qs[j0*QS_S + d0]);
                float q01 = __half2float(qs[j0*QS_S + d0+1]);
                float q10 = __half2float(qs[j1*QS_S + d0]);
                float q11 = __half2float(qs[j1*QS_S + d0+1]);
                va += acc[mi][nt][0]*w0*q00 + acc[mi][nt][2]*w1*q10;
                vb += acc[mi][nt][1]*w0*q01 + acc[mi][nt][3]*w1*q11;
            }
            va += __shfl_xor_sync(0xffffffffu, va, 4);
            va += __shfl_xor_sync(0xffffffffu, va, 8);
            va += __shfl_xor_sync(0xffffffffu, va, 16);
            vb += __shfl_xor_sync(0xffffffffu, vb, 4);
            vb += __shfl_xor_sync(0xffffffffu, vb, 8);
            vb += __shfl_xor_sync(0xffffffffu, vb, 16);
            if (lr == 0) {
                atomicAdd(ph + d0,     va);
                atomicAdd(ph + d0 + 1, vb);
            }
        }
    }
    __syncthreads();

    // -------- fused tail: out[b,:] += ph @ Wo[h*256:,:] (+ bo once) --------
    {
        int wd = wid >> 3;
        int wn = wid & 7;
        int n = wn*32 + lane;
        const float* wop = Wo + ((size_t)(h*HD + wd*128))*HD + n;
        const float* php = ph + wd*128;
        float f0 = 0.f, f1 = 0.f, f2 = 0.f, f3 = 0.f;
        #pragma unroll
        for (int d = 0; d < 128; d += 4) {
            f0 += php[d]   * wop[(size_t)(d  )*HD];
            f1 += php[d+1] * wop[(size_t)(d+1)*HD];
            f2 += php[d+2] * wop[(size_t)(d+2)*HD];
            f3 += php[d+3] * wop[(size_t)(d+3)*HD];
        }
        float f = (f0 + f1) + (f2 + f3);
        if (wd == 0 && (bid & 15) == 0) f += bo[n];
        atomicAdd(&out[b*HD + n], f);
    }
}

// ============================================================
extern "C" void kernel_launch(void* const* d_in, const int* in_sizes, int n_in,
                              void* d_out, int out_size)
{
    const float* v  = (const float*)d_in[0];
    const float* q  = (const float*)d_in[1];
    const float* Wv = (const float*)d_in[2];
    const float* bv = (const float*)d_in[3];
    const float* Wq = (const float*)d_in[4];
    const float* bq = (const float*)d_in[5];
    const float* wa = (const float*)d_in[6];
    // d_in[7] = ba : constant shift before softmax -> drops out
    const float* Wo = (const float*)d_in[8];
    const float* bo = (const float*)d_in[9];
    float* out = (float*)d_out;

    const int SSM = 222464;
    cudaFuncSetAttribute(ban_k, cudaFuncAttributeMaxDynamicSharedMemorySize, SSM);
    ban_k<<<NCTA, 512, SSM>>>(v, q, Wv, Wq, bv, bq, wa, Wo, bo, out);
}